// round 7
// baseline (speedup 1.0000x reference)
#include <cuda_runtime.h>
#include <math.h>

#define T_STEPS 64
#define BATCH   512
#define NIMG    (T_STEPS*BATCH)   // 32768
#define NPAIR   (NIMG/2)          // 16384 image pairs
#define HID     112
#define G4      448               // 4*HID
#define NB      (BATCH*10)        // 5120 LSTM rows
#define LSTM_BLOCKS 128
#define ROWS_PER_BLK 40
#define RPT 10

typedef unsigned long long ull;

// ---- f32x2 helpers ----
__device__ __forceinline__ ull pack2(float lo, float hi) {
    ull r;
    asm("mov.b64 %0, {%1, %2};" : "=l"(r) : "r"(__float_as_uint(lo)), "r"(__float_as_uint(hi)));
    return r;
}
__device__ __forceinline__ ull dup2(float v) { return pack2(v, v); }
__device__ __forceinline__ void fma2(ull& d, ull a, ull b) {
    asm("fma.rn.f32x2 %0, %1, %2, %0;" : "+l"(d) : "l"(a), "l"(b));
}
__device__ __forceinline__ void unpack2(ull v, float& lo, float& hi) {
    unsigned ulo, uhi;
    asm("mov.b64 {%0, %1}, %2;" : "=r"(ulo), "=r"(uhi) : "l"(v));
    lo = __uint_as_float(ulo); hi = __uint_as_float(uhi);
}

__device__ __forceinline__ float fsig(float x) {
    return __fdividef(1.f, 1.f + __expf(-x));
}
__device__ __forceinline__ float ftanh(float x) {
    float e = __expf(2.f * x);
    return 1.f - __fdividef(2.f, e + 1.f);
}

// ---- scratch ----
// g_feat1: paired layout [pair][ic(10)][pos(144)] as float2(imgA,imgB)
__device__ float g_feat1[(size_t)NIMG * 10 * 144];
// g_feat2: paired layout [pair][ic(20)][pos(36)] as float2
__device__ float g_feat2[(size_t)NIMG * 20 * 36];
__device__ float g_x   [(size_t)NIMG * 360];         // standard per-image layout
__device__ float g_gx  [(size_t)T_STEPS * NB * G4];
__device__ float g_whhT[HID * G4];

// ---------------------------------------------------------------------------
__global__ void k_transpose(const float* __restrict__ whh) {
    int idx = blockIdx.x * 256 + threadIdx.x;
    if (idx < HID * G4) {
        int k = idx / G4, col = idx % G4;
        g_whhT[idx] = whh[col * HID + k];
    }
}

// ---------------------------------------------------------------------------
// conv1: (N,1,24,24) -> relu -> pool2 -> paired g_feat1. 1 pair (2 imgs)/block.
// ---------------------------------------------------------------------------
__global__ void k_conv1(const float* __restrict__ imgs,
                        const float* __restrict__ w1, const float* __restrict__ b1) {
    __shared__ float sin_[2 * 576];
    __shared__ float sw[90];
    __shared__ float sb[10];
    int tid = threadIdx.x;
    size_t P = blockIdx.x;            // pair index
    const float* src = imgs + P * 2 * 576;
    for (int i = tid; i < 1152; i += 256) sin_[i] = src[i];
    if (tid < 90) sw[tid] = w1[tid];
    if (tid < 10) sb[tid] = b1[tid];
    __syncthreads();

    for (int it = tid; it < 288; it += 256) {
        int ii = it / 144, p = it % 144;
        int ph = p / 12, pw = p % 12;
        int y0 = 2 * ph - 1, x0 = 2 * pw - 1;
        float patch[4][4];
        #pragma unroll
        for (int dy = 0; dy < 4; dy++) {
            int y = y0 + dy;
            #pragma unroll
            for (int dx = 0; dx < 4; dx++) {
                int x = x0 + dx;
                patch[dy][dx] = (y >= 0 && y < 24 && x >= 0 && x < 24)
                                ? sin_[ii * 576 + y * 24 + x] : 0.f;
            }
        }
        ull pp[4][3];
        #pragma unroll
        for (int r = 0; r < 4; r++)
            #pragma unroll
            for (int dx = 0; dx < 3; dx++)
                pp[r][dx] = pack2(patch[r][dx], patch[r][dx + 1]);

        for (int oc = 0; oc < 10; oc++) {
            float w[9];
            #pragma unroll
            for (int q = 0; q < 9; q++) w[q] = sw[oc * 9 + q];
            float bb = sb[oc];
            ull acc0 = dup2(bb), acc1 = dup2(bb);
            #pragma unroll
            for (int dy = 0; dy < 3; dy++)
                #pragma unroll
                for (int dx = 0; dx < 3; dx++) {
                    ull wd = dup2(w[dy * 3 + dx]);
                    fma2(acc0, pp[dy][dx], wd);
                    fma2(acc1, pp[dy + 1][dx], wd);
                }
            float v00, v01, v10, v11;
            unpack2(acc0, v00, v01); unpack2(acc1, v10, v11);
            float mx = fmaxf(fmaxf(fmaxf(v00, v01), fmaxf(v10, v11)), 0.f);
            // paired layout: component ii of float2 at [P][oc][p]
            g_feat1[(((P * 10 + oc) * 144 + p) << 1) + ii] = mx;
        }
    }
}

// ---------------------------------------------------------------------------
// conv2: paired (pair,10,12,12) -> relu -> pool2 -> paired (pair,20,6,6).
// 2 pairs (4 images)/block, 240 threads. f32x2 lanes = image pair.
// SMEM rows zero-padded: colIdx 0..15 <-> col -1..14 (cols 12..14 zero).
// ---------------------------------------------------------------------------
__global__ void __launch_bounds__(240, 2)
k_conv2(const float* __restrict__ w2, const float* __restrict__ b2) {
    __shared__ __align__(16) float2 spad[2 * 10 * 12 * 16];  // 30720 B
    __shared__ float sw[1800];
    __shared__ float sb[20];
    int tid = threadIdx.x;
    size_t P0 = (size_t)blockIdx.x * 2;
    const float2* src = (const float2*)g_feat1;

    for (int i = tid; i < 3840; i += 240) {
        int pl = i / 1920;
        int ic = (i / 192) % 10;
        int row = (i / 16) % 12;
        int col = (i % 16) - 1;
        float2 v = make_float2(0.f, 0.f);
        if (col >= 0 && col < 12)
            v = src[((P0 + pl) * 10 + ic) * 144 + row * 12 + col];
        spad[i] = v;
    }
    for (int i = tid; i < 1800; i += 240) sw[i] = w2[i];
    if (tid < 20) sb[tid] = b2[tid];
    __syncthreads();

    int pl   = tid / 120;        // pair within block
    int rem  = tid % 120;
    int og   = rem / 12;         // 0..9 -> oc pair
    int rr   = rem % 12;
    int ph   = rr / 2;           // pooled row 0..5
    int half = rr % 2;           // pooled cols 3h..3h+2

    ull acc[2][3][2][2];         // [oc][pw][subrow][subcol], lanes = images
    #pragma unroll
    for (int o = 0; o < 2; o++) {
        ull bb = dup2(sb[2 * og + o]);
        #pragma unroll
        for (int pw = 0; pw < 3; pw++)
            #pragma unroll
            for (int r = 0; r < 2; r++)
                #pragma unroll
                for (int s = 0; s < 2; s++) acc[o][pw][r][s] = bb;
    }

    #pragma unroll 1
    for (int ic = 0; ic < 10; ic++) {
        const float2* rb = spad + (pl * 10 + ic) * 12 * 16;
        ull wd[2][9];
        #pragma unroll
        for (int o = 0; o < 2; o++) {
            const float* wp = sw + ((2 * og + o) * 10 + ic) * 9;
            #pragma unroll
            for (int q = 0; q < 9; q++) wd[o][q] = dup2(wp[q]);
        }
        #pragma unroll
        for (int dy = 0; dy < 4; dy++) {
            int y = 2 * ph - 1 + dy;
            ull v[8];
            if (y >= 0 && y < 12) {
                const ulonglong2* rp = (const ulonglong2*)(rb + y * 16 + 6 * half);
                ulonglong2 a = rp[0], b = rp[1], c2 = rp[2], d = rp[3];
                v[0] = a.x; v[1] = a.y; v[2] = b.x; v[3] = b.y;
                v[4] = c2.x; v[5] = c2.y; v[6] = d.x; v[7] = d.y;
            } else {
                #pragma unroll
                for (int k = 0; k < 8; k++) v[k] = 0ull;
            }
            #pragma unroll
            for (int r = 0; r < 2; r++) {
                int ky = dy - r;
                if (ky >= 0 && ky < 3) {
                    #pragma unroll
                    for (int o = 0; o < 2; o++)
                        #pragma unroll
                        for (int pw = 0; pw < 3; pw++)
                            #pragma unroll
                            for (int s = 0; s < 2; s++)
                                #pragma unroll
                                for (int dx = 0; dx < 3; dx++)
                                    fma2(acc[o][pw][r][s], v[2 * pw + s + dx], wd[o][ky * 3 + dx]);
                }
            }
        }
    }

    float2* dst = (float2*)g_feat2;
    #pragma unroll
    for (int o = 0; o < 2; o++)
        #pragma unroll
        for (int pw = 0; pw < 3; pw++) {
            float a00, b00, a01, b01, a10, b10, a11, b11;
            unpack2(acc[o][pw][0][0], a00, b00);
            unpack2(acc[o][pw][0][1], a01, b01);
            unpack2(acc[o][pw][1][0], a10, b10);
            unpack2(acc[o][pw][1][1], a11, b11);
            float mA = fmaxf(fmaxf(fmaxf(a00, a01), fmaxf(a10, a11)), 0.f);
            float mB = fmaxf(fmaxf(fmaxf(b00, b01), fmaxf(b10, b11)), 0.f);
            dst[((P0 + pl) * 20 + 2 * og + o) * 36 + ph * 6 + 3 * half + pw] =
                make_float2(mA, mB);
        }
}

// ---------------------------------------------------------------------------
// conv3: paired (pair,20,6,6) -> relu -> pool2 -> g_x (standard layout).
// 4 pairs (8 images)/block, 240 threads. Rows padded: colIdx 0..7 <-> col -1..6.
// Dynamic SMEM for the padded input tile.
// ---------------------------------------------------------------------------
__global__ void __launch_bounds__(240, 2)
k_conv3(const float* __restrict__ w3, const float* __restrict__ b3) {
    extern __shared__ __align__(16) float2 spad3[];   // 4*20*6*8 = 3840 float2
    __shared__ float sw[7200];
    __shared__ float sb[40];
    int tid = threadIdx.x;
    size_t P0 = (size_t)blockIdx.x * 4;
    const float2* src = (const float2*)g_feat2;

    for (int i = tid; i < 3840; i += 240) {
        int pl = i / 960;
        int ic = (i / 48) % 20;
        int row = (i / 8) % 6;
        int col = (i % 8) - 1;
        float2 v = make_float2(0.f, 0.f);
        if (col >= 0 && col < 6)
            v = src[((P0 + pl) * 20 + ic) * 36 + row * 6 + col];
        spad3[i] = v;
    }
    for (int i = tid; i < 7200; i += 240) sw[i] = w3[i];
    if (tid < 40) sb[tid] = b3[tid];
    __syncthreads();

    int pl  = tid / 60;          // 0..3
    int rem = tid % 60;
    int og  = rem / 3;           // 0..19 -> oc pair
    int ph  = rem % 3;           // pooled row

    ull acc[2][3][2][2];
    #pragma unroll
    for (int o = 0; o < 2; o++) {
        ull bb = dup2(sb[2 * og + o]);
        #pragma unroll
        for (int pw = 0; pw < 3; pw++)
            #pragma unroll
            for (int r = 0; r < 2; r++)
                #pragma unroll
                for (int s = 0; s < 2; s++) acc[o][pw][r][s] = bb;
    }

    #pragma unroll 1
    for (int ic = 0; ic < 20; ic++) {
        const float2* rb = spad3 + (pl * 20 + ic) * 6 * 8;
        ull wd[2][9];
        #pragma unroll
        for (int o = 0; o < 2; o++) {
            const float* wp = sw + ((2 * og + o) * 20 + ic) * 9;
            #pragma unroll
            for (int q = 0; q < 9; q++) wd[o][q] = dup2(wp[q]);
        }
        #pragma unroll
        for (int dy = 0; dy < 4; dy++) {
            int y = 2 * ph - 1 + dy;
            ull v[8];
            if (y >= 0 && y < 6) {
                const ulonglong2* rp = (const ulonglong2*)(rb + y * 8);
                ulonglong2 a = rp[0], b = rp[1], c2 = rp[2], d = rp[3];
                v[0] = a.x; v[1] = a.y; v[2] = b.x; v[3] = b.y;
                v[4] = c2.x; v[5] = c2.y; v[6] = d.x; v[7] = d.y;
            } else {
                #pragma unroll
                for (int k = 0; k < 8; k++) v[k] = 0ull;
            }
            #pragma unroll
            for (int r = 0; r < 2; r++) {
                int ky = dy - r;
                if (ky >= 0 && ky < 3) {
                    #pragma unroll
                    for (int o = 0; o < 2; o++)
                        #pragma unroll
                        for (int pw = 0; pw < 3; pw++)
                            #pragma unroll
                            for (int s = 0; s < 2; s++)
                                #pragma unroll
                                for (int dx = 0; dx < 3; dx++)
                                    fma2(acc[o][pw][r][s], v[2 * pw + s + dx], wd[o][ky * 3 + dx]);
                }
            }
        }
    }

    size_t imgA = (P0 + pl) * 2;
    #pragma unroll
    for (int o = 0; o < 2; o++)
        #pragma unroll
        for (int pw = 0; pw < 3; pw++) {
            float a00, b00, a01, b01, a10, b10, a11, b11;
            unpack2(acc[o][pw][0][0], a00, b00);
            unpack2(acc[o][pw][0][1], a01, b01);
            unpack2(acc[o][pw][1][0], a10, b10);
            unpack2(acc[o][pw][1][1], a11, b11);
            float mA = fmaxf(fmaxf(fmaxf(a00, a01), fmaxf(a10, a11)), 0.f);
            float mB = fmaxf(fmaxf(fmaxf(b00, b01), fmaxf(b10, b11)), 0.f);
            int off = (2 * og + o) * 9 + ph * 3 + pw;
            g_x[imgA * 360 + off]       = mA;
            g_x[(imgA + 1) * 360 + off] = mB;
        }
}

// ---------------------------------------------------------------------------
// gates_x: (327680,36) @ (36,448) + biases. f32x2 over row pairs.
// ---------------------------------------------------------------------------
__global__ void __launch_bounds__(448, 1)
k_gatesx(const float* __restrict__ w_ih,
         const float* __restrict__ b_ih, const float* __restrict__ b_hh) {
    __shared__ __align__(16) float sxp[36 * 32 * 2];
    int j = threadIdx.x;
    size_t row0 = (size_t)blockIdx.x * 64;
    const float* src = g_x + row0 * 36;
    for (int i = j; i < 2304; i += 448) {
        int row = i / 36, k = i % 36;
        sxp[(k * 32 + (row >> 1)) * 2 + (row & 1)] = src[i];
    }
    ull wd[36];
    {
        const float4* wp = (const float4*)(w_ih + j * 36);
        #pragma unroll
        for (int q = 0; q < 9; q++) {
            float4 v = wp[q];
            wd[4 * q] = dup2(v.x); wd[4 * q + 1] = dup2(v.y);
            wd[4 * q + 2] = dup2(v.z); wd[4 * q + 3] = dup2(v.w);
        }
    }
    float bias = b_ih[j] + b_hh[j];
    ull bias2 = dup2(bias);
    __syncthreads();

    const ull* sx2 = (const ull*)sxp;
    for (int rp = 0; rp < 32; rp++) {
        ull acc = bias2;
        #pragma unroll
        for (int k = 0; k < 36; k++)
            fma2(acc, sx2[k * 32 + rp], wd[k]);
        float lo, hi; unpack2(acc, lo, hi);
        g_gx[(row0 + 2 * rp) * G4 + j] = lo;
        g_gx[(row0 + 2 * rp + 1) * G4 + j] = hi;
    }
}

// ---------------------------------------------------------------------------
// Full LSTM recurrence in ONE kernel.
// ---------------------------------------------------------------------------
__global__ void __launch_bounds__(448, 1)
k_lstm(const float* __restrict__ h0, const float* __restrict__ c0,
       const float* __restrict__ wf, const float* __restrict__ bf,
       float* __restrict__ out) {
    extern __shared__ float sm[];
    float* ws = sm;                               // [112][448]
    float2* hs2 = (float2*)(sm + HID * G4);       // [20 pairs][112]
    int tid = threadIdx.x;
    int j = tid % 112, ry = tid / 112;
    int mb = blockIdx.x * ROWS_PER_BLK;

    {
        const float4* wsrc = (const float4*)g_whhT;
        float4* wdst = (float4*)ws;
        for (int i = tid; i < HID * G4 / 4; i += 448) wdst[i] = wsrc[i];
    }
    float c[RPT];
    float h0j = h0[j], c0j = c0[j];
    #pragma unroll
    for (int p = 0; p < 5; p++) hs2[(ry * 5 + p) * 112 + j] = make_float2(h0j, h0j);
    #pragma unroll
    for (int i = 0; i < RPT; i++) c[i] = c0j;
    __syncthreads();

    for (int t = 0; t < T_STEPS; t++) {
        ull accp[5][4];
        #pragma unroll
        for (int p = 0; p < 5; p++)
            #pragma unroll
            for (int g = 0; g < 4; g++) accp[p][g] = 0ull;

        const ulonglong2* hv2 = (const ulonglong2*)hs2;
        #pragma unroll 2
        for (int kq = 0; kq < 56; kq++) {
            int k = kq * 2;
            ulonglong2 hv[5];
            #pragma unroll
            for (int p = 0; p < 5; p++)
                hv[p] = hv2[((ry * 5 + p) * 112 + k) >> 1];
            const float* wk = ws + k * G4 + j;
            ull wd0[4], wd1[4];
            #pragma unroll
            for (int g = 0; g < 4; g++) {
                wd0[g] = dup2(wk[g * 112]);
                wd1[g] = dup2(wk[G4 + g * 112]);
            }
            #pragma unroll
            for (int p = 0; p < 5; p++)
                #pragma unroll
                for (int g = 0; g < 4; g++) {
                    fma2(accp[p][g], hv[p].x, wd0[g]);
                    fma2(accp[p][g], hv[p].y, wd1[g]);
                }
        }
        __syncthreads();

        const float* gxb = g_gx + ((size_t)t * NB + mb + ry * RPT) * G4 + j;
        #pragma unroll
        for (int p = 0; p < 5; p++) {
            float a0[4], a1[4];
            #pragma unroll
            for (int g = 0; g < 4; g++) unpack2(accp[p][g], a0[g], a1[g]);
            const float* gp0 = gxb + (size_t)(2 * p) * G4;
            const float* gp1 = gp0 + G4;

            float I0 = fsig(a0[0] + gp0[0]);
            float F0 = fsig(a0[1] + gp0[112]);
            float G0 = ftanh(a0[2] + gp0[224]);
            float O0 = fsig(a0[3] + gp0[336]);
            c[2 * p] = fmaf(F0, c[2 * p], I0 * G0);
            float hA = O0 * ftanh(c[2 * p]);

            float I1 = fsig(a1[0] + gp1[0]);
            float F1 = fsig(a1[1] + gp1[112]);
            float G1 = ftanh(a1[2] + gp1[224]);
            float O1 = fsig(a1[3] + gp1[336]);
            c[2 * p + 1] = fmaf(F1, c[2 * p + 1], I1 * G1);
            float hB = O1 * ftanh(c[2 * p + 1]);

            hs2[(ry * 5 + p) * 112 + j] = make_float2(hA, hB);
        }
        __syncthreads();
    }

    if (tid < ROWS_PER_BLK) {
        int pair = tid >> 1, comp = tid & 1;
        float l[3];
        #pragma unroll
        for (int o = 0; o < 3; o++) {
            float a = bf[o];
            const float* wo = wf + o * 112;
            #pragma unroll 4
            for (int k = 0; k < 112; k++) {
                float2 v = hs2[pair * 112 + k];
                a = fmaf(comp ? v.y : v.x, wo[k], a);
            }
            l[o] = a;
        }
        float m = fmaxf(l[0], fmaxf(l[1], l[2]));
        float e0 = expf(l[0] - m), e1 = expf(l[1] - m), e2 = expf(l[2] - m);
        float s = 1.f / (e0 + e1 + e2);
        float* op = out + (size_t)(mb + tid) * 3;
        op[0] = e0 * s; op[1] = e1 * s; op[2] = e2 * s;
    }
}

// ---------------------------------------------------------------------------
extern "C" void kernel_launch(void* const* d_in, const int* in_sizes, int n_in,
                              void* d_out, int out_size) {
    const float* imgs = (const float*)d_in[0];
    const float* w1   = (const float*)d_in[1];
    const float* b1   = (const float*)d_in[2];
    const float* w2   = (const float*)d_in[3];
    const float* b2   = (const float*)d_in[4];
    const float* w3   = (const float*)d_in[5];
    const float* b3   = (const float*)d_in[6];
    const float* w_ih = (const float*)d_in[7];
    const float* w_hh = (const float*)d_in[8];
    const float* b_ih = (const float*)d_in[9];
    const float* b_hh = (const float*)d_in[10];
    const float* wf   = (const float*)d_in[11];
    const float* bf   = (const float*)d_in[12];
    const float* h0   = (const float*)d_in[13];
    const float* c0   = (const float*)d_in[14];

    const int lstm_smem  = HID * G4 * 4 + 20 * 112 * 8;  // 218,624 B
    const int conv3_smem = 3840 * 8;                     // 30,720 B dynamic
    cudaFuncSetAttribute(k_lstm, cudaFuncAttributeMaxDynamicSharedMemorySize, lstm_smem);
    cudaFuncSetAttribute(k_conv3, cudaFuncAttributeMaxDynamicSharedMemorySize, conv3_smem);

    k_transpose<<<(HID * G4 + 255) / 256, 256>>>(w_hh);
    k_conv1<<<NPAIR, 256>>>(imgs, w1, b1);
    k_conv2<<<NPAIR / 2, 240>>>(w2, b2);
    k_conv3<<<NPAIR / 4, 240, conv3_smem>>>(w3, b3);
    k_gatesx<<<(T_STEPS * NB) / 64, 448>>>(w_ih, b_ih, b_hh);
    k_lstm<<<LSTM_BLOCKS, 448, lstm_smem>>>(h0, c0, wf, bf, (float*)d_out);
}

// round 8
// speedup vs baseline: 1.0434x; 1.0434x over previous
#include <cuda_runtime.h>
#include <math.h>

#define T_STEPS 64
#define BATCH   512
#define NIMG    (T_STEPS*BATCH)   // 32768
#define HID     112
#define G4      448               // 4*HID
#define NB      (BATCH*10)        // 5120 LSTM rows
#define LSTM_THREADS 336          // 112 j x 3 row-groups
#define LROWS   36                // rows per LSTM block
#define LSTM_BLOCKS 143           // ceil(5120/36); last block has 8 rows

typedef unsigned long long ull;

// ---- f32x2 helpers ----
__device__ __forceinline__ ull pack2(float lo, float hi) {
    ull r;
    asm("mov.b64 %0, {%1, %2};" : "=l"(r) : "r"(__float_as_uint(lo)), "r"(__float_as_uint(hi)));
    return r;
}
__device__ __forceinline__ ull dup2(float v) { return pack2(v, v); }
__device__ __forceinline__ void fma2(ull& d, ull a, ull b) {
    asm("fma.rn.f32x2 %0, %1, %2, %0;" : "+l"(d) : "l"(a), "l"(b));
}
__device__ __forceinline__ void unpack2(ull v, float& lo, float& hi) {
    unsigned ulo, uhi;
    asm("mov.b64 {%0, %1}, %2;" : "=r"(ulo), "=r"(uhi) : "l"(v));
    lo = __uint_as_float(ulo); hi = __uint_as_float(uhi);
}

__device__ __forceinline__ float fsig(float x) {
    return __fdividef(1.f, 1.f + __expf(-x));
}
__device__ __forceinline__ float ftanh(float x) {
    float e = __expf(2.f * x);
    return 1.f - __fdividef(2.f, e + 1.f);
}

// ---- scratch ----
__device__ float g_feat1[(size_t)NIMG * 10 * 144];
__device__ float g_feat2[(size_t)NIMG * 20 * 36];
__device__ float g_x   [(size_t)NIMG * 360];
// g_gx layout: [row][jj*4 + gate]  (gates interleaved per hidden unit -> float4 loads)
__device__ float g_gx  [(size_t)T_STEPS * NB * G4];
__device__ float g_whhT[HID * G4];

// ---------------------------------------------------------------------------
__global__ void k_transpose(const float* __restrict__ whh) {
    int idx = blockIdx.x * 256 + threadIdx.x;
    if (idx < HID * G4) {
        int k = idx / G4, col = idx % G4;
        g_whhT[idx] = whh[col * HID + k];
    }
}

// ---------------------------------------------------------------------------
// conv1: (N,1,24,24) -> relu -> pool2 -> (N,10,12,12). 16 images/block,
// 2304 items = 9 per thread exactly; weights amortized 9x.
// ---------------------------------------------------------------------------
__global__ void __launch_bounds__(256, 2)
k_conv1(const float* __restrict__ imgs,
        const float* __restrict__ w1, const float* __restrict__ b1) {
    __shared__ __align__(16) float sin_[16 * 576];   // 36864 B
    __shared__ float sw[90];
    __shared__ float sb[10];
    int tid = threadIdx.x;
    size_t img0 = (size_t)blockIdx.x * 16;
    {
        const float4* src = (const float4*)(imgs + img0 * 576);
        float4* dst = (float4*)sin_;
        #pragma unroll
        for (int k = 0; k < 9; k++) dst[tid + k * 256] = src[tid + k * 256];
    }
    if (tid < 90) sw[tid] = w1[tid];
    if (tid < 10) sb[tid] = b1[tid];
    __syncthreads();

    #pragma unroll 1
    for (int k = 0; k < 9; k++) {
        int it = tid + k * 256;            // 0..2303
        int ii = it / 144, p = it % 144;
        int ph = p / 12, pw = p % 12;
        int y0 = 2 * ph - 1, x0 = 2 * pw - 1;
        float patch[4][4];
        #pragma unroll
        for (int dy = 0; dy < 4; dy++) {
            int y = y0 + dy;
            #pragma unroll
            for (int dx = 0; dx < 4; dx++) {
                int x = x0 + dx;
                patch[dy][dx] = (y >= 0 && y < 24 && x >= 0 && x < 24)
                                ? sin_[ii * 576 + y * 24 + x] : 0.f;
            }
        }
        ull pp[4][3];
        #pragma unroll
        for (int r = 0; r < 4; r++)
            #pragma unroll
            for (int dx = 0; dx < 3; dx++)
                pp[r][dx] = pack2(patch[r][dx], patch[r][dx + 1]);

        size_t obase = (img0 + ii) * 1440;
        #pragma unroll 1
        for (int oc = 0; oc < 10; oc++) {
            float w[9];
            #pragma unroll
            for (int q = 0; q < 9; q++) w[q] = sw[oc * 9 + q];
            float bb = sb[oc];
            ull acc0 = dup2(bb), acc1 = dup2(bb);
            #pragma unroll
            for (int dy = 0; dy < 3; dy++)
                #pragma unroll
                for (int dx = 0; dx < 3; dx++) {
                    ull wd = dup2(w[dy * 3 + dx]);
                    fma2(acc0, pp[dy][dx], wd);
                    fma2(acc1, pp[dy + 1][dx], wd);
                }
            float v00, v01, v10, v11;
            unpack2(acc0, v00, v01); unpack2(acc1, v10, v11);
            float mx = fmaxf(fmaxf(v00, v01), fmaxf(v10, v11));
            g_feat1[obase + oc * 144 + p] = fmaxf(mx, 0.f);
        }
    }
}

// ---------------------------------------------------------------------------
// conv2: (N,10,12,12) -> relu -> pool2 -> (N,20,6,6). 2 images / block.
// (R5 structure — measured best)
// ---------------------------------------------------------------------------
__global__ void __launch_bounds__(256, 1)
k_conv2(const float* __restrict__ w2, const float* __restrict__ b2) {
    __shared__ __align__(16) float sin_[2 * 1440];
    __shared__ float sw[1800];
    __shared__ float sb[20];
    int tid = threadIdx.x;
    size_t img0 = (size_t)blockIdx.x * 2;
    const float* src = g_feat1 + img0 * 1440;
    for (int i = tid; i < 2880; i += 256) sin_[i] = src[i];
    for (int i = tid; i < 1800; i += 256) sw[i] = w2[i];
    if (tid < 20) sb[tid] = b2[tid];
    __syncthreads();

    if (tid >= 240) return;
    int ii   = tid / 120;
    int rem  = tid % 120;
    int og   = rem / 12;
    int rr   = rem % 12;
    int ph   = rr / 2;
    int half = rr % 2;

    ull acc[2][3][2];
    #pragma unroll
    for (int o = 0; o < 2; o++) {
        ull bb = dup2(sb[2 * og + o]);
        #pragma unroll
        for (int pw = 0; pw < 3; pw++) { acc[o][pw][0] = bb; acc[o][pw][1] = bb; }
    }

    const float* base = sin_ + ii * 1440;
    #pragma unroll 1
    for (int ic = 0; ic < 10; ic++) {
        const float* sp = base + ic * 144;
        float v[4][8];
        #pragma unroll
        for (int dy = 0; dy < 4; dy++) {
            int y = 2 * ph - 1 + dy;
            if (y >= 0 && y < 12) {
                const float4* rp = (const float4*)(sp + y * 12);
                float4 a = rp[half];
                float4 b = rp[half + 1];
                if (!half) {
                    v[dy][0] = 0.f;  v[dy][1] = a.x; v[dy][2] = a.y; v[dy][3] = a.z;
                    v[dy][4] = a.w;  v[dy][5] = b.x; v[dy][6] = b.y; v[dy][7] = b.z;
                } else {
                    v[dy][0] = a.y;  v[dy][1] = a.z; v[dy][2] = a.w; v[dy][3] = b.x;
                    v[dy][4] = b.y;  v[dy][5] = b.z; v[dy][6] = b.w; v[dy][7] = 0.f;
                }
            } else {
                #pragma unroll
                for (int k = 0; k < 8; k++) v[dy][k] = 0.f;
            }
        }
        ull pk[4][7];
        #pragma unroll
        for (int dy = 0; dy < 4; dy++)
            #pragma unroll
            for (int cc = 0; cc < 7; cc++)
                pk[dy][cc] = pack2(v[dy][cc], v[dy][cc + 1]);

        #pragma unroll
        for (int o = 0; o < 2; o++) {
            const float* wp = sw + ((2 * og + o) * 10 + ic) * 9;
            ull wd[9];
            #pragma unroll
            for (int q = 0; q < 9; q++) wd[q] = dup2(wp[q]);
            #pragma unroll
            for (int pw = 0; pw < 3; pw++)
                #pragma unroll
                for (int r = 0; r < 2; r++)
                    #pragma unroll
                    for (int dy = 0; dy < 3; dy++)
                        #pragma unroll
                        for (int dx = 0; dx < 3; dx++)
                            fma2(acc[o][pw][r], pk[r + dy][2 * pw + dx], wd[dy * 3 + dx]);
        }
    }

    size_t obase = (img0 + ii) * 720;
    #pragma unroll
    for (int o = 0; o < 2; o++)
        #pragma unroll
        for (int pw = 0; pw < 3; pw++) {
            float v00, v01, v10, v11;
            unpack2(acc[o][pw][0], v00, v01);
            unpack2(acc[o][pw][1], v10, v11);
            float mx = fmaxf(fmaxf(v00, v01), fmaxf(v10, v11));
            g_feat2[obase + (2 * og + o) * 36 + ph * 6 + 3 * half + pw] = fmaxf(mx, 0.f);
        }
}

// ---------------------------------------------------------------------------
// conv3: (N,20,6,6) -> relu -> pool2 -> (N,40,3,3) -> g_x. 4 images / block.
// (R5 structure — measured best)
// ---------------------------------------------------------------------------
__global__ void __launch_bounds__(256, 1)
k_conv3(const float* __restrict__ w3, const float* __restrict__ b3) {
    __shared__ __align__(16) float sin_[4 * 720];
    __shared__ float sw[7200];
    __shared__ float sb[40];
    int tid = threadIdx.x;
    size_t img0 = (size_t)blockIdx.x * 4;
    const float* src = g_feat2 + img0 * 720;
    for (int i = tid; i < 2880; i += 256) sin_[i] = src[i];
    for (int i = tid; i < 7200; i += 256) sw[i] = w3[i];
    if (tid < 40) sb[tid] = b3[tid];
    __syncthreads();

    if (tid >= 240) return;
    int ii  = tid / 60;
    int rem = tid % 60;
    int og  = rem / 3;
    int ph  = rem % 3;

    ull acc[2][3][2];
    #pragma unroll
    for (int o = 0; o < 2; o++) {
        ull bb = dup2(sb[2 * og + o]);
        #pragma unroll
        for (int pw = 0; pw < 3; pw++) { acc[o][pw][0] = bb; acc[o][pw][1] = bb; }
    }

    const float* base = sin_ + ii * 720;
    #pragma unroll 1
    for (int ic = 0; ic < 20; ic++) {
        const float* sp = base + ic * 36;
        float v[4][8];
        #pragma unroll
        for (int dy = 0; dy < 4; dy++) {
            int y = 2 * ph - 1 + dy;
            if (y >= 0 && y < 6) {
                const float2* rp = (const float2*)(sp + y * 6);
                float2 r0 = rp[0], r1 = rp[1], r2 = rp[2];
                v[dy][0] = 0.f;  v[dy][1] = r0.x; v[dy][2] = r0.y; v[dy][3] = r1.x;
                v[dy][4] = r1.y; v[dy][5] = r2.x; v[dy][6] = r2.y; v[dy][7] = 0.f;
            } else {
                #pragma unroll
                for (int k = 0; k < 8; k++) v[dy][k] = 0.f;
            }
        }
        ull pk[4][7];
        #pragma unroll
        for (int dy = 0; dy < 4; dy++)
            #pragma unroll
            for (int cc = 0; cc < 7; cc++)
                pk[dy][cc] = pack2(v[dy][cc], v[dy][cc + 1]);

        #pragma unroll
        for (int o = 0; o < 2; o++) {
            const float* wp = sw + ((2 * og + o) * 20 + ic) * 9;
            ull wd[9];
            #pragma unroll
            for (int q = 0; q < 9; q++) wd[q] = dup2(wp[q]);
            #pragma unroll
            for (int pw = 0; pw < 3; pw++)
                #pragma unroll
                for (int r = 0; r < 2; r++)
                    #pragma unroll
                    for (int dy = 0; dy < 3; dy++)
                        #pragma unroll
                        for (int dx = 0; dx < 3; dx++)
                            fma2(acc[o][pw][r], pk[r + dy][2 * pw + dx], wd[dy * 3 + dx]);
        }
    }

    size_t obase = (img0 + ii) * 360;
    #pragma unroll
    for (int o = 0; o < 2; o++)
        #pragma unroll
        for (int pw = 0; pw < 3; pw++) {
            float v00, v01, v10, v11;
            unpack2(acc[o][pw][0], v00, v01);
            unpack2(acc[o][pw][1], v10, v11);
            float mx = fmaxf(fmaxf(v00, v01), fmaxf(v10, v11));
            g_x[obase + (2 * og + o) * 9 + ph * 3 + pw] = fmaxf(mx, 0.f);
        }
}

// ---------------------------------------------------------------------------
// gates_x: (327680,36) @ (36,448) + biases. f32x2 over row pairs.
// Stores interleaved: g_gx[row*448 + jj*4 + gate]  (float4 per hidden unit).
// ---------------------------------------------------------------------------
__global__ void __launch_bounds__(448, 1)
k_gatesx(const float* __restrict__ w_ih,
         const float* __restrict__ b_ih, const float* __restrict__ b_hh) {
    __shared__ __align__(16) float sxp[36 * 32 * 2];
    int j = threadIdx.x;                 // 0..447
    int jj = j % 112, g = j / 112;
    int outoff = jj * 4 + g;
    size_t row0 = (size_t)blockIdx.x * 64;
    const float* src = g_x + row0 * 36;
    for (int i = j; i < 2304; i += 448) {
        int row = i / 36, k = i % 36;
        sxp[(k * 32 + (row >> 1)) * 2 + (row & 1)] = src[i];
    }
    ull wd[36];
    {
        const float4* wp = (const float4*)(w_ih + j * 36);
        #pragma unroll
        for (int q = 0; q < 9; q++) {
            float4 v = wp[q];
            wd[4 * q] = dup2(v.x); wd[4 * q + 1] = dup2(v.y);
            wd[4 * q + 2] = dup2(v.z); wd[4 * q + 3] = dup2(v.w);
        }
    }
    float bias = b_ih[j] + b_hh[j];
    ull bias2 = dup2(bias);
    __syncthreads();

    const ull* sx2 = (const ull*)sxp;
    for (int rp = 0; rp < 32; rp++) {
        ull acc = bias2;
        #pragma unroll
        for (int k = 0; k < 36; k++)
            fma2(acc, sx2[k * 32 + rp], wd[k]);
        float lo, hi; unpack2(acc, lo, hi);
        g_gx[(row0 + 2 * rp) * G4 + outoff] = lo;
        g_gx[(row0 + 2 * rp + 1) * G4 + outoff] = hi;
    }
}

// ---------------------------------------------------------------------------
// Full LSTM recurrence in ONE kernel. 336 threads (3 row-groups x RPT 12),
// 36 rows x 143 blocks (1 wave on 143 SMs; last block 8 rows via guards).
// gx prefetched as float4 at step top (hidden under the GEMM).
// ---------------------------------------------------------------------------
__global__ void __launch_bounds__(LSTM_THREADS, 1)
k_lstm(const float* __restrict__ h0, const float* __restrict__ c0,
       const float* __restrict__ wf, const float* __restrict__ bf,
       float* __restrict__ out) {
    extern __shared__ float sm[];
    float* ws = sm;                               // [112][448]
    float2* hs2 = (float2*)(sm + HID * G4);       // [18 pairs][112]
    int tid = threadIdx.x;
    int j = tid % 112, ry = tid / 112;            // ry 0..2
    int mb = blockIdx.x * LROWS;

    {
        const float4* wsrc = (const float4*)g_whhT;
        float4* wdst = (float4*)ws;
        for (int i = tid; i < HID * G4 / 4; i += LSTM_THREADS) wdst[i] = wsrc[i];
    }
    float c[12];
    float h0j = h0[j], c0j = c0[j];
    #pragma unroll
    for (int p = 0; p < 6; p++) hs2[(ry * 6 + p) * 112 + j] = make_float2(h0j, h0j);
    #pragma unroll
    for (int i = 0; i < 12; i++) c[i] = c0j;

    int  rA[6];
    bool valid[6];
    #pragma unroll
    for (int p = 0; p < 6; p++) {
        rA[p] = mb + 2 * (ry * 6 + p);
        valid[p] = rA[p] < NB;
    }
    __syncthreads();

    for (int t = 0; t < T_STEPS; t++) {
        // ---- prefetch gx for this step (hidden under the GEMM below) ----
        float4 gA[6], gB[6];
        size_t tb = (size_t)t * NB;
        #pragma unroll
        for (int p = 0; p < 6; p++) {
            int ra = valid[p] ? rA[p] : 0;
            int rb = valid[p] ? rA[p] + 1 : 0;
            gA[p] = ((const float4*)(g_gx + (tb + ra) * G4))[j];
            gB[p] = ((const float4*)(g_gx + (tb + rb) * G4))[j];
        }

        ull accp[6][4];
        #pragma unroll
        for (int p = 0; p < 6; p++)
            #pragma unroll
            for (int g = 0; g < 4; g++) accp[p][g] = 0ull;

        const ulonglong2* hv2 = (const ulonglong2*)hs2;
        #pragma unroll 2
        for (int kq = 0; kq < 56; kq++) {
            int k = kq * 2;
            ulonglong2 hv[6];
            #pragma unroll
            for (int p = 0; p < 6; p++)
                hv[p] = hv2[((ry * 6 + p) * 112 + k) >> 1];
            const float* wk = ws + k * G4 + j;
            ull wd0[4], wd1[4];
            #pragma unroll
            for (int g = 0; g < 4; g++) {
                wd0[g] = dup2(wk[g * 112]);
                wd1[g] = dup2(wk[G4 + g * 112]);
            }
            #pragma unroll
            for (int p = 0; p < 6; p++)
                #pragma unroll
                for (int g = 0; g < 4; g++) {
                    fma2(accp[p][g], hv[p].x, wd0[g]);
                    fma2(accp[p][g], hv[p].y, wd1[g]);
                }
        }
        __syncthreads();

        #pragma unroll
        for (int p = 0; p < 6; p++) {
            float a0[4], a1[4];
            #pragma unroll
            for (int g = 0; g < 4; g++) unpack2(accp[p][g], a0[g], a1[g]);

            float I0 = fsig(a0[0] + gA[p].x);
            float F0 = fsig(a0[1] + gA[p].y);
            float G0 = ftanh(a0[2] + gA[p].z);
            float O0 = fsig(a0[3] + gA[p].w);
            c[2 * p] = fmaf(F0, c[2 * p], I0 * G0);
            float hA = O0 * ftanh(c[2 * p]);

            float I1 = fsig(a1[0] + gB[p].x);
            float F1 = fsig(a1[1] + gB[p].y);
            float G1 = ftanh(a1[2] + gB[p].z);
            float O1 = fsig(a1[3] + gB[p].w);
            c[2 * p + 1] = fmaf(F1, c[2 * p + 1], I1 * G1);
            float hB = O1 * ftanh(c[2 * p + 1]);

            hs2[(ry * 6 + p) * 112 + j] = make_float2(hA, hB);
        }
        __syncthreads();
    }

    // fused final: softmax(h @ wf^T + bf)
    if (tid < LROWS && mb + tid < NB) {
        int pair = tid >> 1, comp = tid & 1;
        float l[3];
        #pragma unroll
        for (int o = 0; o < 3; o++) {
            float a = bf[o];
            const float* wo = wf + o * 112;
            #pragma unroll 4
            for (int k = 0; k < 112; k++) {
                float2 v = hs2[pair * 112 + k];
                a = fmaf(comp ? v.y : v.x, wo[k], a);
            }
            l[o] = a;
        }
        float m = fmaxf(l[0], fmaxf(l[1], l[2]));
        float e0 = expf(l[0] - m), e1 = expf(l[1] - m), e2 = expf(l[2] - m);
        float s = 1.f / (e0 + e1 + e2);
        float* op = out + (size_t)(mb + tid) * 3;
        op[0] = e0 * s; op[1] = e1 * s; op[2] = e2 * s;
    }
}

// ---------------------------------------------------------------------------
extern "C" void kernel_launch(void* const* d_in, const int* in_sizes, int n_in,
                              void* d_out, int out_size) {
    const float* imgs = (const float*)d_in[0];
    const float* w1   = (const float*)d_in[1];
    const float* b1   = (const float*)d_in[2];
    const float* w2   = (const float*)d_in[3];
    const float* b2   = (const float*)d_in[4];
    const float* w3   = (const float*)d_in[5];
    const float* b3   = (const float*)d_in[6];
    const float* w_ih = (const float*)d_in[7];
    const float* w_hh = (const float*)d_in[8];
    const float* b_ih = (const float*)d_in[9];
    const float* b_hh = (const float*)d_in[10];
    const float* wf   = (const float*)d_in[11];
    const float* bf   = (const float*)d_in[12];
    const float* h0   = (const float*)d_in[13];
    const float* c0   = (const float*)d_in[14];

    const int lstm_smem = HID * G4 * 4 + 18 * 112 * 8;   // 216,832 B
    cudaFuncSetAttribute(k_lstm, cudaFuncAttributeMaxDynamicSharedMemorySize, lstm_smem);

    k_transpose<<<(HID * G4 + 255) / 256, 256>>>(w_hh);
    k_conv1<<<NIMG / 16, 256>>>(imgs, w1, b1);
    k_conv2<<<NIMG / 2, 256>>>(w2, b2);
    k_conv3<<<NIMG / 4, 256>>>(w3, b3);
    k_gatesx<<<(T_STEPS * NB) / 64, 448>>>(w_ih, b_ih, b_hh);
    k_lstm<<<LSTM_BLOCKS, LSTM_THREADS, lstm_smem>>>(h0, c0, wf, bf, (float*)d_out);
}